// round 2
// baseline (speedup 1.0000x reference)
#include <cuda_runtime.h>
#include <math.h>

// Problem constants (fixed shapes from the reference)
#define B 128
#define C 512
#define HW 1024            // 32*32
#define E 16
#define KTOP 2
#define NOISE_STD_INV 16.0f   // 1 / (1/E) = E
#define TAU 1.0f
#define EPS 1e-8f

// Scratch (no allocations allowed in kernel_launch)
__device__ float g_pooled[B * C];   // 256 KB

// ---------------------------------------------------------------------------
// Kernel 1: adaptive avg pool.  One warp per (b,c) row of 1024 contiguous f32.
// Loads are front-batched into a register array to maximize in-flight MLP.
// ---------------------------------------------------------------------------
__global__ void __launch_bounds__(256) pool_kernel(const float* __restrict__ x) {
    int gwarp = (blockIdx.x * blockDim.x + threadIdx.x) >> 5;
    int lane  = threadIdx.x & 31;

    const float4* row = reinterpret_cast<const float4*>(x + (size_t)gwarp * HW);
    float4 v[8];
#pragma unroll
    for (int j = 0; j < 8; ++j) v[j] = __ldg(&row[lane + 32 * j]);

    float s = 0.0f;
#pragma unroll
    for (int j = 0; j < 8; ++j) s += (v[j].x + v[j].y) + (v[j].z + v[j].w);

#pragma unroll
    for (int o = 16; o; o >>= 1) s += __shfl_xor_sync(0xffffffffu, s, o);
    if (lane == 0) g_pooled[gwarp] = s * (1.0f / (float)HW);
}

// ---------------------------------------------------------------------------
// Kernel 2 (fused): gate GEMM + softmaxes + top-2 + gates scatter + aux loss.
// Single block of 1024 threads.  W_gate staged in smem; logits in smem.
// Deterministic reductions (no float atomics) -> bitwise stable per replay.
// ---------------------------------------------------------------------------
__global__ void __launch_bounds__(1024) gate_finalize_kernel(
        const float* __restrict__ Wg,
        const float* __restrict__ complexity,
        const float* __restrict__ noise,
        float* __restrict__ out) {
    __shared__ float sW[E * C];        // 32 KB
    __shared__ float sLog[B * E];      // 8 KB logits
    __shared__ float sm_clean[B][E];   // 8 KB clean softmax probs
    __shared__ float sm_p[B][E];       // 8 KB load-balance p values
    __shared__ float sh_imp[E];
    __shared__ float sh_pm[E];

    int tid = threadIdx.x;

    // Stage W_gate into smem (8192 floats / 1024 threads = 8 each, float4)
    {
        const float4* src = reinterpret_cast<const float4*>(Wg);
        float4*       dst = reinterpret_cast<float4*>(sW);
#pragma unroll
        for (int j = 0; j < 2; ++j) dst[tid + 1024 * j] = __ldg(&src[tid + 1024 * j]);
    }
    __syncthreads();

    // GEMM: 2048 (b,e) dot products, 2 per thread.
    // Thread layout t -> b = t>>4, e = t&15 : warp reads 2 distinct pooled
    // addresses per iteration (broadcast), W from smem.
#pragma unroll
    for (int pair = 0; pair < 2; ++pair) {
        int t = tid + pair * 1024;
        int b = t >> 4;
        int e = t & 15;
        const float* prow = g_pooled + b * C;
        const float* wrow = sW + e * C;
        float s = 0.0f;
#pragma unroll 8
        for (int c = 0; c < C; ++c) s = fmaf(prow[c], wrow[c], s);
        sLog[t] = s;
    }
    __syncthreads();

    int b = tid;
    if (b < B) {
        float l[E], n[E];
#pragma unroll
        for (int e = 0; e < E; ++e) {
            l[e] = sLog[b * E + e];
            n[e] = l[e] + noise[b * E + e];
        }
        // clean softmax
        {
            float mx = l[0];
#pragma unroll
            for (int e = 1; e < E; ++e) mx = fmaxf(mx, l[e]);
            float ssum = 0.0f, t2[E];
#pragma unroll
            for (int e = 0; e < E; ++e) { t2[e] = expf(l[e] - mx); ssum += t2[e]; }
            float inv = 1.0f / ssum;
#pragma unroll
            for (int e = 0; e < E; ++e) sm_clean[b][e] = t2[e] * inv;
        }
        // noisy softmax
        float g[E];
        {
            float mx = n[0];
#pragma unroll
            for (int e = 1; e < E; ++e) mx = fmaxf(mx, n[e]);
            float ssum = 0.0f;
#pragma unroll
            for (int e = 0; e < E; ++e) { g[e] = expf(n[e] - mx); ssum += g[e]; }
            float inv = 1.0f / ssum;
#pragma unroll
            for (int e = 0; e < E; ++e) g[e] *= inv;
        }
        // top-2 (strict > => lowest index wins ties, matching jax.lax.top_k)
        int i1 = 0;
#pragma unroll
        for (int e = 1; e < E; ++e) if (g[e] > g[i1]) i1 = e;
        int i2 = (i1 == 0) ? 1 : 0;
#pragma unroll
        for (int e = 0; e < E; ++e) if (e != i1 && g[e] > g[i2]) i2 = e;
        float v1 = g[i1], v2 = g[i2];
        float thr = n[i2];   // 2nd-largest noisy logit

        // gates row + topk outputs
#pragma unroll
        for (int e = 0; e < E; ++e)
            out[b * E + e] = (e == i1) ? v1 : ((e == i2) ? v2 : 0.0f);
        out[B * E + b * KTOP + 0]            = (float)i1;
        out[B * E + b * KTOP + 1]            = (float)i2;
        out[B * E + B * KTOP + b * KTOP + 0] = v1;
        out[B * E + B * KTOP + b * KTOP + 1] = v2;

        // p[e] = 1 - Phi((thr - l[e]) / sigma) = 0.5 * erfc(z / sqrt(2))
#pragma unroll
        for (int e = 0; e < E; ++e) {
            float z = (thr - l[e]) * NOISE_STD_INV;
            sm_p[b][e] = 0.5f * erfcf(z * 0.70710678118654752f);
        }
    }
    __syncthreads();

    if (tid < E) {
        int e = tid;
        float si = 0.0f, sp = 0.0f;
        for (int bb = 0; bb < B; ++bb) { si += sm_clean[bb][e]; sp += sm_p[bb][e]; }
        sh_imp[e] = si * (complexity[e] * TAU);
        sh_pm[e]  = sp * (1.0f / (float)B);
    }
    __syncthreads();

    if (tid == 0) {
        float mi = 0.0f, mp = 0.0f;
#pragma unroll
        for (int e = 0; e < E; ++e) { mi += sh_imp[e]; mp += sh_pm[e]; }
        mi *= (1.0f / (float)E);
        mp *= (1.0f / (float)E);
        float vi = 0.0f, vp = 0.0f;
#pragma unroll
        for (int e = 0; e < E; ++e) {
            float di = sh_imp[e] - mi; vi += di * di;
            float dp = sh_pm[e]  - mp; vp += dp * dp;
        }
        vi *= (1.0f / (float)(E - 1));   // ddof=1
        vp *= (1.0f / (float)(E - 1));
        float cvi = sqrtf(vi) / (mi + EPS);
        float cvp = sqrtf(vp) / (mp + EPS);
        out[B * E + 2 * B * KTOP] = 0.5f * (cvi * cvi) + 0.5f * (cvp * cvp);
    }
}

// ---------------------------------------------------------------------------
extern "C" void kernel_launch(void* const* d_in, const int* in_sizes, int n_in,
                              void* d_out, int out_size) {
    const float* x          = (const float*)d_in[0];
    const float* W_gate     = (const float*)d_in[1];
    const float* complexity = (const float*)d_in[2];
    const float* noise      = (const float*)d_in[3];
    float* out = (float*)d_out;

    // 1 warp per (b,c) row; 8 warps per block -> 8192 blocks
    pool_kernel<<<B * C / 8, 256>>>(x);
    gate_finalize_kernel<<<1, 1024>>>(W_gate, complexity, noise, out);
}

// round 3
// speedup vs baseline: 1.7049x; 1.7049x over previous
#include <cuda_runtime.h>
#include <math.h>

// Problem constants (fixed shapes from the reference)
#define B 128
#define C 512
#define HW 1024            // 32*32
#define E 16
#define KTOP 2
#define NOISE_STD_INV 16.0f   // 1 / (1/E) = E
#define TAU 1.0f
#define EPS 1e-8f

// Scratch (no allocations allowed in kernel_launch)
__device__ float g_pooled[B * C];   // 256 KB

// ---------------------------------------------------------------------------
// Kernel 1: adaptive avg pool.  One warp per TWO (b,c) rows (1024 f32 each).
// 16 independent LDG.128 per thread, front-batched for max MLP.
// ---------------------------------------------------------------------------
__global__ void __launch_bounds__(256) pool_kernel(const float* __restrict__ x) {
    int gwarp = (blockIdx.x * blockDim.x + threadIdx.x) >> 5;  // warp id
    int lane  = threadIdx.x & 31;
    int row0  = gwarp * 2;

    const float4* r0 = reinterpret_cast<const float4*>(x + (size_t)row0 * HW);
    const float4* r1 = reinterpret_cast<const float4*>(x + (size_t)(row0 + 1) * HW);

    float4 v[16];
#pragma unroll
    for (int j = 0; j < 8; ++j) v[j]     = __ldg(&r0[lane + 32 * j]);
#pragma unroll
    for (int j = 0; j < 8; ++j) v[8 + j] = __ldg(&r1[lane + 32 * j]);

    float s0 = 0.0f, s1 = 0.0f;
#pragma unroll
    for (int j = 0; j < 8; ++j) s0 += (v[j].x + v[j].y) + (v[j].z + v[j].w);
#pragma unroll
    for (int j = 0; j < 8; ++j) s1 += (v[8 + j].x + v[8 + j].y) + (v[8 + j].z + v[8 + j].w);

#pragma unroll
    for (int o = 16; o; o >>= 1) {
        s0 += __shfl_xor_sync(0xffffffffu, s0, o);
        s1 += __shfl_xor_sync(0xffffffffu, s1, o);
    }
    if (lane == 0) {
        g_pooled[row0]     = s0 * (1.0f / (float)HW);
        g_pooled[row0 + 1] = s1 * (1.0f / (float)HW);
    }
}

// ---------------------------------------------------------------------------
// Kernel 2 (fused): gate GEMM + softmaxes + top-2 + gates scatter + aux loss.
// Single block of 1024 threads (32 warps).
// GEMM: each warp owns 4 batch rows; lanes span C (coalesced LDG, pooled row
// in registers, sW read as float4 at consecutive lane addresses -> NO bank
// conflicts).  Deterministic reductions -> bitwise stable per replay.
// ---------------------------------------------------------------------------
__global__ void __launch_bounds__(1024) gate_finalize_kernel(
        const float* __restrict__ Wg,
        const float* __restrict__ complexity,
        const float* __restrict__ noise,
        float* __restrict__ out) {
    __shared__ float sW[E * C];        // 32 KB
    __shared__ float sLog[B * E];      // 8 KB logits
    __shared__ float sm_clean[B][E];   // 8 KB clean softmax probs
    __shared__ float sm_p[B][E];       // 8 KB load-balance p values
    __shared__ float sh_imp[E];
    __shared__ float sh_pm[E];

    int tid  = threadIdx.x;
    int warp = tid >> 5;
    int lane = tid & 31;

    // Stage W_gate into smem (8192 floats / 1024 threads = 8 each, float4)
    {
        const float4* src = reinterpret_cast<const float4*>(Wg);
        float4*       dst = reinterpret_cast<float4*>(sW);
#pragma unroll
        for (int j = 0; j < 2; ++j) dst[tid + 1024 * j] = __ldg(&src[tid + 1024 * j]);
    }
    __syncthreads();

    // GEMM: warp handles batch rows 4*warp .. 4*warp+3.
    const float4* sW4 = reinterpret_cast<const float4*>(sW);
#pragma unroll
    for (int r = 0; r < 4; ++r) {
        int b = warp * 4 + r;
        const float4* prow = reinterpret_cast<const float4*>(g_pooled + b * C);
        float4 p[4];
#pragma unroll
        for (int j = 0; j < 4; ++j) p[j] = prow[lane + 32 * j];  // coalesced L2

#pragma unroll
        for (int e = 0; e < E; ++e) {
            const float4* wrow = sW4 + e * (C / 4);
            float s = 0.0f;
#pragma unroll
            for (int j = 0; j < 4; ++j) {
                float4 w = wrow[lane + 32 * j];   // conflict-free LDS.128
                s = fmaf(p[j].x, w.x, s);
                s = fmaf(p[j].y, w.y, s);
                s = fmaf(p[j].z, w.z, s);
                s = fmaf(p[j].w, w.w, s);
            }
#pragma unroll
            for (int o = 16; o; o >>= 1) s += __shfl_xor_sync(0xffffffffu, s, o);
            if (lane == 0) sLog[b * E + e] = s;
        }
    }
    __syncthreads();

    int b = tid;
    if (b < B) {
        float l[E], n[E];
#pragma unroll
        for (int e = 0; e < E; ++e) {
            l[e] = sLog[b * E + e];
            n[e] = l[e] + noise[b * E + e];
        }
        // clean softmax
        {
            float mx = l[0];
#pragma unroll
            for (int e = 1; e < E; ++e) mx = fmaxf(mx, l[e]);
            float ssum = 0.0f, t2[E];
#pragma unroll
            for (int e = 0; e < E; ++e) { t2[e] = expf(l[e] - mx); ssum += t2[e]; }
            float inv = 1.0f / ssum;
#pragma unroll
            for (int e = 0; e < E; ++e) sm_clean[b][e] = t2[e] * inv;
        }
        // noisy softmax
        float g[E];
        {
            float mx = n[0];
#pragma unroll
            for (int e = 1; e < E; ++e) mx = fmaxf(mx, n[e]);
            float ssum = 0.0f;
#pragma unroll
            for (int e = 0; e < E; ++e) { g[e] = expf(n[e] - mx); ssum += g[e]; }
            float inv = 1.0f / ssum;
#pragma unroll
            for (int e = 0; e < E; ++e) g[e] *= inv;
        }
        // top-2 (strict > => lowest index wins ties, matching jax.lax.top_k)
        int i1 = 0;
#pragma unroll
        for (int e = 1; e < E; ++e) if (g[e] > g[i1]) i1 = e;
        int i2 = (i1 == 0) ? 1 : 0;
#pragma unroll
        for (int e = 0; e < E; ++e) if (e != i1 && g[e] > g[i2]) i2 = e;
        float v1 = g[i1], v2 = g[i2];
        float thr = n[i2];   // 2nd-largest noisy logit

        // gates row + topk outputs
#pragma unroll
        for (int e = 0; e < E; ++e)
            out[b * E + e] = (e == i1) ? v1 : ((e == i2) ? v2 : 0.0f);
        out[B * E + b * KTOP + 0]            = (float)i1;
        out[B * E + b * KTOP + 1]            = (float)i2;
        out[B * E + B * KTOP + b * KTOP + 0] = v1;
        out[B * E + B * KTOP + b * KTOP + 1] = v2;

        // p[e] = 1 - Phi((thr - l[e]) / sigma) = 0.5 * erfc(z / sqrt(2))
#pragma unroll
        for (int e = 0; e < E; ++e) {
            float z = (thr - l[e]) * NOISE_STD_INV;
            sm_p[b][e] = 0.5f * erfcf(z * 0.70710678118654752f);
        }
    }
    __syncthreads();

    if (tid < E) {
        int e = tid;
        float si = 0.0f, sp = 0.0f;
        for (int bb = 0; bb < B; ++bb) { si += sm_clean[bb][e]; sp += sm_p[bb][e]; }
        sh_imp[e] = si * (complexity[e] * TAU);
        sh_pm[e]  = sp * (1.0f / (float)B);
    }
    __syncthreads();

    if (tid == 0) {
        float mi = 0.0f, mp = 0.0f;
#pragma unroll
        for (int e = 0; e < E; ++e) { mi += sh_imp[e]; mp += sh_pm[e]; }
        mi *= (1.0f / (float)E);
        mp *= (1.0f / (float)E);
        float vi = 0.0f, vp = 0.0f;
#pragma unroll
        for (int e = 0; e < E; ++e) {
            float di = sh_imp[e] - mi; vi += di * di;
            float dp = sh_pm[e]  - mp; vp += dp * dp;
        }
        vi *= (1.0f / (float)(E - 1));   // ddof=1
        vp *= (1.0f / (float)(E - 1));
        float cvi = sqrtf(vi) / (mi + EPS);
        float cvp = sqrtf(vp) / (mp + EPS);
        out[B * E + 2 * B * KTOP] = 0.5f * (cvi * cvi) + 0.5f * (cvp * cvp);
    }
}

// ---------------------------------------------------------------------------
extern "C" void kernel_launch(void* const* d_in, const int* in_sizes, int n_in,
                              void* d_out, int out_size) {
    const float* x          = (const float*)d_in[0];
    const float* W_gate     = (const float*)d_in[1];
    const float* complexity = (const float*)d_in[2];
    const float* noise      = (const float*)d_in[3];
    float* out = (float*)d_out;

    // 2 rows per warp, 8 warps per block -> 4096 blocks
    pool_kernel<<<B * C / 16, 256>>>(x);
    gate_finalize_kernel<<<1, 1024>>>(W_gate, complexity, noise, out);
}

// round 4
// speedup vs baseline: 3.8851x; 2.2787x over previous
#include <cuda_runtime.h>
#include <math.h>

// Problem constants (fixed shapes from the reference)
#define B 128
#define C 512
#define HW 1024            // 32*32
#define E 16
#define KTOP 2
#define NOISE_STD_INV 16.0f   // 1 / (1/E) = E
#define TAU 1.0f
#define EPS 1e-8f

// Scratch (no allocations allowed in kernel_launch)
__device__ float g_logits[B * E];
__device__ unsigned int g_counter = 0;   // reset by last block each launch

// ---------------------------------------------------------------------------
// Fully fused kernel: grid = B blocks, 1024 threads.
// Block b: pool 512 rows -> smem, gate GEMM -> g_logits[b,:], then the LAST
// block to finish (atomic ticket) runs softmax/top-2/aux-loss finalize.
// All float reductions are order-deterministic (no float atomics).
// ---------------------------------------------------------------------------
__global__ void __launch_bounds__(1024) fused_kernel(
        const float* __restrict__ x,
        const float* __restrict__ Wg,
        const float* __restrict__ complexity,
        const float* __restrict__ noise,
        float* __restrict__ out) {
    __shared__ float spooled[C];       // 2 KB
    __shared__ float sm_clean[B][E];   // 8 KB
    __shared__ float sm_p[B][E];       // 8 KB
    __shared__ float sh_imp[E];
    __shared__ float sh_pm[E];
    __shared__ int   s_is_last;

    const int tid  = threadIdx.x;
    const int w    = tid >> 5;
    const int lane = tid & 31;
    const int b    = blockIdx.x;

    // ---- Phase 1: pool.  Warp w owns rows w*16 .. w*16+15 (contiguous 64KB).
    const float* xb = x + ((size_t)b * C + (size_t)w * 16) * HW;
#pragma unroll 1
    for (int i = 0; i < 16; ++i) {
        const float4* r = reinterpret_cast<const float4*>(xb + (size_t)i * HW);
        float4 v[8];
#pragma unroll
        for (int j = 0; j < 8; ++j) v[j] = __ldg(&r[lane + 32 * j]);
        float s = 0.0f;
#pragma unroll
        for (int j = 0; j < 8; ++j) s += (v[j].x + v[j].y) + (v[j].z + v[j].w);
#pragma unroll
        for (int o = 16; o; o >>= 1) s += __shfl_xor_sync(0xffffffffu, s, o);
        if (lane == 0) spooled[w * 16 + i] = s * (1.0f / (float)HW);
    }
    __syncthreads();

    // ---- Phase 2: gate GEMM.  Warps 0..15 -> one expert each, lanes over C.
    if (w < E) {
        const float* wrow = Wg + w * C;
        float s = 0.0f;
#pragma unroll
        for (int j = 0; j < C / 32; ++j) {
            int c = lane + 32 * j;                 // conflict-free smem banks
            s = fmaf(spooled[c], __ldg(&wrow[c]), s);
        }
#pragma unroll
        for (int o = 16; o; o >>= 1) s += __shfl_xor_sync(0xffffffffu, s, o);
        if (lane == 0) {
            g_logits[b * E + w] = s;
            __threadfence();                       // publish before ticket
        }
    }
    __syncthreads();

    // ---- Ticket: last block runs finalize.
    if (tid == 0) {
        unsigned int t = atomicAdd(&g_counter, 1u);
        s_is_last = (t == (unsigned int)(gridDim.x - 1));
    }
    __syncthreads();
    if (!s_is_last) return;
    __threadfence();   // acquire: make all blocks' logits visible

    // ---- Phase 3 (last block only): softmaxes, top-2, gates, aux loss.
    const int bb = tid;
    if (bb < B) {
        float l[E], n[E];
#pragma unroll
        for (int e = 0; e < E; ++e) {
            l[e] = g_logits[bb * E + e];
            n[e] = l[e] + noise[bb * E + e];
        }
        // clean softmax
        {
            float mx = l[0];
#pragma unroll
            for (int e = 1; e < E; ++e) mx = fmaxf(mx, l[e]);
            float ssum = 0.0f, t2[E];
#pragma unroll
            for (int e = 0; e < E; ++e) { t2[e] = expf(l[e] - mx); ssum += t2[e]; }
            float inv = 1.0f / ssum;
#pragma unroll
            for (int e = 0; e < E; ++e) sm_clean[bb][e] = t2[e] * inv;
        }
        // noisy softmax
        float g[E];
        {
            float mx = n[0];
#pragma unroll
            for (int e = 1; e < E; ++e) mx = fmaxf(mx, n[e]);
            float ssum = 0.0f;
#pragma unroll
            for (int e = 0; e < E; ++e) { g[e] = expf(n[e] - mx); ssum += g[e]; }
            float inv = 1.0f / ssum;
#pragma unroll
            for (int e = 0; e < E; ++e) g[e] *= inv;
        }
        // top-2 (strict > => lowest index wins ties, matching jax.lax.top_k)
        int i1 = 0;
#pragma unroll
        for (int e = 1; e < E; ++e) if (g[e] > g[i1]) i1 = e;
        int i2 = (i1 == 0) ? 1 : 0;
#pragma unroll
        for (int e = 0; e < E; ++e) if (e != i1 && g[e] > g[i2]) i2 = e;
        float v1 = g[i1], v2 = g[i2];
        float thr = n[i2];   // 2nd-largest noisy logit

        // gates row + topk outputs
#pragma unroll
        for (int e = 0; e < E; ++e)
            out[bb * E + e] = (e == i1) ? v1 : ((e == i2) ? v2 : 0.0f);
        out[B * E + bb * KTOP + 0]            = (float)i1;
        out[B * E + bb * KTOP + 1]            = (float)i2;
        out[B * E + B * KTOP + bb * KTOP + 0] = v1;
        out[B * E + B * KTOP + bb * KTOP + 1] = v2;

        // p[e] = 1 - Phi((thr - l[e]) / sigma) = 0.5 * erfc(z / sqrt(2))
#pragma unroll
        for (int e = 0; e < E; ++e) {
            float z = (thr - l[e]) * NOISE_STD_INV;
            sm_p[bb][e] = 0.5f * erfcf(z * 0.70710678118654752f);
        }
    }
    __syncthreads();

    if (tid < E) {
        int e = tid;
        float si = 0.0f, sp = 0.0f;
        for (int r = 0; r < B; ++r) { si += sm_clean[r][e]; sp += sm_p[r][e]; }
        sh_imp[e] = si * (complexity[e] * TAU);
        sh_pm[e]  = sp * (1.0f / (float)B);
    }
    __syncthreads();

    if (tid == 0) {
        float mi = 0.0f, mp = 0.0f;
#pragma unroll
        for (int e = 0; e < E; ++e) { mi += sh_imp[e]; mp += sh_pm[e]; }
        mi *= (1.0f / (float)E);
        mp *= (1.0f / (float)E);
        float vi = 0.0f, vp = 0.0f;
#pragma unroll
        for (int e = 0; e < E; ++e) {
            float di = sh_imp[e] - mi; vi += di * di;
            float dp = sh_pm[e]  - mp; vp += dp * dp;
        }
        vi *= (1.0f / (float)(E - 1));   // ddof=1
        vp *= (1.0f / (float)(E - 1));
        float cvi = sqrtf(vi) / (mi + EPS);
        float cvp = sqrtf(vp) / (mp + EPS);
        out[B * E + 2 * B * KTOP] = 0.5f * (cvi * cvi) + 0.5f * (cvp * cvp);

        g_counter = 0;   // reset ticket for next graph replay
    }
}

// ---------------------------------------------------------------------------
extern "C" void kernel_launch(void* const* d_in, const int* in_sizes, int n_in,
                              void* d_out, int out_size) {
    const float* x          = (const float*)d_in[0];
    const float* W_gate     = (const float*)d_in[1];
    const float* complexity = (const float*)d_in[2];
    const float* noise      = (const float*)d_in[3];
    float* out = (float*)d_out;

    fused_kernel<<<B, 1024>>>(x, W_gate, complexity, noise, out);
}